// round 14
// baseline (speedup 1.0000x reference)
#include <cuda_runtime.h>

// SpikingCell recurrence, simplified (R1 derivation):
//   clamp gate always-true -> dropped; spike counter unused -> dropped
//   per (b,n):  v += (refrac>=2) ? x[t-1] : 0 ; out=(v>=1); v-=out;
//               refrac = out ? 0 : refrac+1
// Pure streaming: 128MiB in + 128MiB out, zero reuse, nonlinear recurrence
// (no scan reformulation) -> traffic is irreducible.
//
// FINAL — best measured, reproduced 3x at 45.5us harness / 38.1-38.7us
// kernel / ~5.6TB/s. Full lever sweep (grain 32/64/128b, pipeline depth
// 8/16, store burstiness, __ldlu, L2 residency default+evict_last,
// write-through stores) was neutral-to-negative: the binding constraint is
// the DRAM mixed-R/W ceiling for a 50/50 256MiB stream (~70% of spec BW;
// residual is channel R/W turnaround, not software-addressable — chip-wide
// phase segregation costs more in grid barriers than it recovers).
//
// Config: float2/thread (LDG.64/STG.64), 1024 blocks x 64 threads
// (6.92 blocks/SM, ~1.2% wave imbalance), ping-pong register pipeline PF=8
// (structural MLP, immune to ptxas scheduling), evict-first hints on both
// streams so the streaming traffic recycles L2 among itself.

constexpr int B = 16, T = 256, N = 8192;
constexpr int N2 = N / 2;                  // float2 lanes per row = 4096
constexpr int THREADS = 64;
constexpr int GRID = (B * N2) / THREADS;   // 1024 blocks
constexpr int PF = 8;                      // pipeline depth (float2 steps)
constexpr int NBATCH = T / PF;             // 32 batches -> 16 ping-pong pairs

__device__ __forceinline__ void step(float2 d, float& v0, float& v1,
                                     int& r0, int& r1, float2& o)
{
    v0 += (r0 >= 2) ? d.x : 0.f;
    o.x = (v0 >= 1.f) ? 1.f : 0.f;
    v0 -= o.x;
    r0 = (o.x != 0.f) ? 0 : (r0 + 1);

    v1 += (r1 >= 2) ? d.y : 0.f;
    o.y = (v1 >= 1.f) ? 1.f : 0.f;
    v1 -= o.y;
    r1 = (o.y != 0.f) ? 0 : (r1 + 1);
}

__global__ __launch_bounds__(THREADS) void spiking_kernel(
    const float2* __restrict__ x, float2* __restrict__ out)
{
    int tid = blockIdx.x * THREADS + threadIdx.x;   // 0 .. B*N2-1
    int b = tid >> 12;            // / N2
    int c = tid & (N2 - 1);       // % N2
    size_t base = (size_t)b * T * N2 + c;

    const float2* __restrict__ xp = x + base;
    float2* __restrict__ op = out + base;

    float v0 = 0.f, v1 = 0.f;     // membrane potentials
    int   r0 = 0,   r1 = 0;       // refractory counters
    float2 d = make_float2(0.f, 0.f);   // dv buffer (x[t-1])

    float2 bufA[PF], bufB[PF];

    // prologue: fill A
#pragma unroll
    for (int i = 0; i < PF; i++) bufA[i] = __ldcs(xp + (size_t)i * N2);
    xp += (size_t)PF * N2;

#pragma unroll 1
    for (int pair = 0; pair < NBATCH / 2 - 1; pair++) {
        // load B, compute+store A
#pragma unroll
        for (int i = 0; i < PF; i++) bufB[i] = __ldcs(xp + (size_t)i * N2);
        xp += (size_t)PF * N2;
#pragma unroll
        for (int i = 0; i < PF; i++) {
            float2 o;
            step(d, v0, v1, r0, r1, o);
            __stcs(op, o); op += N2;
            d = bufA[i];
        }
        // load A, compute+store B
#pragma unroll
        for (int i = 0; i < PF; i++) bufA[i] = __ldcs(xp + (size_t)i * N2);
        xp += (size_t)PF * N2;
#pragma unroll
        for (int i = 0; i < PF; i++) {
            float2 o;
            step(d, v0, v1, r0, r1, o);
            __stcs(op, o); op += N2;
            d = bufB[i];
        }
    }

    // tail: load final B, compute A, then compute B
#pragma unroll
    for (int i = 0; i < PF; i++) bufB[i] = __ldcs(xp + (size_t)i * N2);
#pragma unroll
    for (int i = 0; i < PF; i++) {
        float2 o;
        step(d, v0, v1, r0, r1, o);
        __stcs(op, o); op += N2;
        d = bufA[i];
    }
#pragma unroll
    for (int i = 0; i < PF; i++) {
        float2 o;
        step(d, v0, v1, r0, r1, o);
        __stcs(op, o); op += N2;
        d = bufB[i];
    }
}

extern "C" void kernel_launch(void* const* d_in, const int* in_sizes, int n_in,
                              void* d_out, int out_size)
{
    const float2* x = (const float2*)d_in[0];
    float2* out = (float2*)d_out;
    spiking_kernel<<<GRID, THREADS>>>(x, out);
}

// round 15
// speedup vs baseline: 1.0007x; 1.0007x over previous
#include <cuda_runtime.h>

// SpikingCell recurrence, simplified (R1 derivation):
//   clamp gate always-true -> dropped; spike counter unused -> dropped
//   per (b,n):  v += (refrac>=2) ? x[t-1] : 0 ; out=(v>=1); v-=out;
//               refrac = out ? 0 : refrac+1
// Pure streaming: 128MiB in + 128MiB out, zero reuse, nonlinear recurrence
// (no scan reformulation) -> traffic is irreducible.
//
// FINAL — best measured, reproduced 4x at 45.5-45.6us harness / ~38.4us
// kernel / ~5.6TB/s (~70% of 8TB/s spec = B300's mixed-R/W stream ceiling).
// Sweep results: grain 32/64/128b, depth 8/16, store burstiness, __ldlu,
// L2 residency (default + evict_last), write-through stores — all
// neutral-to-negative. Residual DRAM idle is channel R/W turnaround, not
// software-addressable; chip-wide R/W phase segregation costs more in grid
// barriers than it recovers.
//
// Config: float2/thread (LDG.64/STG.64), 1024 blocks x 64 threads
// (6.92 blocks/SM, ~1.2% wave imbalance), ping-pong register pipeline PF=8
// (structural MLP, immune to ptxas scheduling), evict-first hints on both
// streams so the streaming traffic recycles L2 among itself.

constexpr int B = 16, T = 256, N = 8192;
constexpr int N2 = N / 2;                  // float2 lanes per row = 4096
constexpr int THREADS = 64;
constexpr int GRID = (B * N2) / THREADS;   // 1024 blocks
constexpr int PF = 8;                      // pipeline depth (float2 steps)
constexpr int NBATCH = T / PF;             // 32 batches -> 16 ping-pong pairs

__device__ __forceinline__ void step(float2 d, float& v0, float& v1,
                                     int& r0, int& r1, float2& o)
{
    v0 += (r0 >= 2) ? d.x : 0.f;
    o.x = (v0 >= 1.f) ? 1.f : 0.f;
    v0 -= o.x;
    r0 = (o.x != 0.f) ? 0 : (r0 + 1);

    v1 += (r1 >= 2) ? d.y : 0.f;
    o.y = (v1 >= 1.f) ? 1.f : 0.f;
    v1 -= o.y;
    r1 = (o.y != 0.f) ? 0 : (r1 + 1);
}

__global__ __launch_bounds__(THREADS) void spiking_kernel(
    const float2* __restrict__ x, float2* __restrict__ out)
{
    int tid = blockIdx.x * THREADS + threadIdx.x;   // 0 .. B*N2-1
    int b = tid >> 12;            // / N2
    int c = tid & (N2 - 1);       // % N2
    size_t base = (size_t)b * T * N2 + c;

    const float2* __restrict__ xp = x + base;
    float2* __restrict__ op = out + base;

    float v0 = 0.f, v1 = 0.f;     // membrane potentials
    int   r0 = 0,   r1 = 0;       // refractory counters
    float2 d = make_float2(0.f, 0.f);   // dv buffer (x[t-1])

    float2 bufA[PF], bufB[PF];

    // prologue: fill A
#pragma unroll
    for (int i = 0; i < PF; i++) bufA[i] = __ldcs(xp + (size_t)i * N2);
    xp += (size_t)PF * N2;

#pragma unroll 1
    for (int pair = 0; pair < NBATCH / 2 - 1; pair++) {
        // load B, compute+store A
#pragma unroll
        for (int i = 0; i < PF; i++) bufB[i] = __ldcs(xp + (size_t)i * N2);
        xp += (size_t)PF * N2;
#pragma unroll
        for (int i = 0; i < PF; i++) {
            float2 o;
            step(d, v0, v1, r0, r1, o);
            __stcs(op, o); op += N2;
            d = bufA[i];
        }
        // load A, compute+store B
#pragma unroll
        for (int i = 0; i < PF; i++) bufA[i] = __ldcs(xp + (size_t)i * N2);
        xp += (size_t)PF * N2;
#pragma unroll
        for (int i = 0; i < PF; i++) {
            float2 o;
            step(d, v0, v1, r0, r1, o);
            __stcs(op, o); op += N2;
            d = bufB[i];
        }
    }

    // tail: load final B, compute A, then compute B
#pragma unroll
    for (int i = 0; i < PF; i++) bufB[i] = __ldcs(xp + (size_t)i * N2);
#pragma unroll
    for (int i = 0; i < PF; i++) {
        float2 o;
        step(d, v0, v1, r0, r1, o);
        __stcs(op, o); op += N2;
        d = bufA[i];
    }
#pragma unroll
    for (int i = 0; i < PF; i++) {
        float2 o;
        step(d, v0, v1, r0, r1, o);
        __stcs(op, o); op += N2;
        d = bufB[i];
    }
}

extern "C" void kernel_launch(void* const* d_in, const int* in_sizes, int n_in,
                              void* d_out, int out_size)
{
    const float2* x = (const float2*)d_in[0];
    float2* out = (float2*)d_out;
    spiking_kernel<<<GRID, THREADS>>>(x, out);
}